// round 13
// baseline (speedup 1.0000x reference)
#include <cuda_runtime.h>
#include <cuda_bf16.h>
#include <cuda_fp16.h>
#include <cstdint>

#define NN 100000
#define NE 1600000
#define DDIM 128
#define CAP 64                         // slot capacity per node (max deg ~45)
#define NT 782
#define BN_EPS 1e-5f
#define PA 136                         // bf16 SMEM row pitch for A planes
#define SMEM_BYTES (2 * 128 * PA * 2)  // 69632: two A planes (sZ reuses)

// ---------------- device scratch (static globals: allowed) ----------------
__device__ float g_h[(size_t)NN * DDIM];
__device__ float g_z[(size_t)NN * DDIM];
__device__ __nv_bfloat16 g_Ahi[(size_t)NN * DDIM];
__device__ __nv_bfloat16 g_Alo[(size_t)NN * DDIM];
__device__ int g_cnt[NN];
__device__ int g_srcs[(size_t)NN * CAP];
__device__ __half g_ea16[(size_t)NN * CAP * DDIM];   // slot-CSR fp16 edge_attr
__device__ uint32_t g_Wfrag[6 * 16384];  // 6 matrices, fragment-major
__device__ float g_bsum[3][DDIM];
__device__ float g_bsq[3][DDIM];

// ---------------- helpers ----------------
__device__ __forceinline__ void split2(float a, float b, uint32_t& hi, uint32_t& lo) {
    __nv_bfloat16 ah = __float2bfloat16(a), bh = __float2bfloat16(b);
    __nv_bfloat16 al = __float2bfloat16(a - __bfloat162float(ah));
    __nv_bfloat16 bl = __float2bfloat16(b - __bfloat162float(bh));
    __nv_bfloat162 H; H.x = ah; H.y = bh;
    __nv_bfloat162 L; L.x = al; L.y = bl;
    hi = *reinterpret_cast<uint32_t*>(&H);
    lo = *reinterpret_cast<uint32_t*>(&L);
}

__device__ __forceinline__ uint32_t lds_u32(const __nv_bfloat16* p) {
    return *reinterpret_cast<const uint32_t*>(p);
}

#define MMA16816(d0,d1,d2,d3,a0,a1,a2,a3,b0,b1)                               \
    asm volatile("mma.sync.aligned.m16n8k16.row.col.f32.bf16.bf16.f32 "       \
                 "{%0,%1,%2,%3},{%4,%5,%6,%7},{%8,%9},{%0,%1,%2,%3};"         \
                 : "+f"(d0), "+f"(d1), "+f"(d2), "+f"(d3)                     \
                 : "r"(a0), "r"(a1), "r"(a2), "r"(a3), "r"(b0), "r"(b1))

// ---------------- launch 1: W split + zero counters/BN ----------------
__global__ void k_zero(const float* __restrict__ W1, const float* __restrict__ W2) {
    int i = blockIdx.x * blockDim.x + threadIdx.x;
    if (i < 6 * 16384) {
        int part = i & 3;              // 0=b0h 1=b1h 2=b0l 3=b1l
        int lane = (i >> 2) & 31;
        int fragid = (i >> 7) & 127;   // nt*8 + kk
        int mat = i >> 14;             // l*2 + j
        int l = mat >> 1, j = mat & 1;
        int nt = fragid >> 3, kk = fragid & 7;
        int bn = nt * 8 + (lane >> 2);
        int bk = kk * 16 + (lane & 3) * 2 + (part & 1) * 8;
        const float* Wsrc = (j ? W2 : W1) + (size_t)l * 16384;
        float w0 = Wsrc[bk * 128 + bn];
        float w1 = Wsrc[(bk + 1) * 128 + bn];
        uint32_t hi, lo;
        split2(w0, w1, hi, lo);
        g_Wfrag[i] = (part >= 2) ? lo : hi;
    }
    if (i < NN) g_cnt[i] = 0;
    if (i < 3 * DDIM) {
        ((float*)g_bsum)[i] = 0.f;
        ((float*)g_bsq)[i] = 0.f;
    }
}

// ---------------- launch 2: slot scatter + fp16 convert ----------------
__global__ void k_pre(const int* __restrict__ src, const int* __restrict__ dst,
                      const float* __restrict__ ea) {
    int gwarp = (blockIdx.x * 256 + threadIdx.x) >> 5;
    int lane = threadIdx.x & 31;
    int ebase = gwarp * 4;
    if (ebase >= NE) return;
    int pos = -1, s = 0;
    if (lane < 4 && ebase + lane < NE) {
        int e = ebase + lane;
        int d = __ldg(dst + e);
        int r = atomicAdd(&g_cnt[d], 1);
        if (r < CAP) pos = d * CAP + r;
        s = __ldg(src + e);
    }
    const float4* ea4 = (const float4*)ea;
#pragma unroll
    for (int k = 0; k < 4; k++) {
        int e = ebase + k;
        if (e >= NE) break;
        int p = __shfl_sync(0xffffffff, pos, k);
        if (p < 0) continue;
        if (lane == k) g_srcs[p] = s;
        float4 v = ea4[(size_t)e * 32 + lane];
        __half2 a = __float22half2_rn(make_float2(v.x, v.y));
        __half2 b = __float22half2_rn(make_float2(v.z, v.w));
        uint2 u;
        u.x = *reinterpret_cast<uint32_t*>(&a);
        u.y = *reinterpret_cast<uint32_t*>(&b);
        ((uint2*)g_ea16)[(size_t)p * 32 + lane] = u;
    }
}

// ---------------- aggregation: warp per node, 2x unrolled (round-8) --------
__global__ void k_agg(const float* __restrict__ x, const float* __restrict__ eps,
                      int l, int first) {
    int node = (blockIdx.x * blockDim.x + threadIdx.x) >> 5;
    if (node >= NN) return;
    int lane = threadIdx.x & 31;
    int beg = node * CAP;
    int end = beg + min(g_cnt[node], CAP);
    const float4* hin = (const float4*)(first ? x : g_h);
    const uint2* ea16 = (const uint2*)g_ea16;
    float4 acc = make_float4(0.f, 0.f, 0.f, 0.f);
    int i = beg;
    for (; i + 2 <= end; i += 2) {
        int s0 = g_srcs[i], s1 = g_srcs[i + 1];
        uint2 u0 = __ldcs(&ea16[(size_t)i * 32 + lane]);
        uint2 u1 = __ldcs(&ea16[(size_t)(i + 1) * 32 + lane]);
        float4 h0 = hin[(size_t)s0 * 32 + lane];
        float4 h1 = hin[(size_t)s1 * 32 + lane];
        float2 e0a = __half22float2(*(__half2*)&u0.x);
        float2 e0b = __half22float2(*(__half2*)&u0.y);
        float2 e1a = __half22float2(*(__half2*)&u1.x);
        float2 e1b = __half22float2(*(__half2*)&u1.y);
        acc.x += fmaxf(h0.x + e0a.x, 0.f) + fmaxf(h1.x + e1a.x, 0.f);
        acc.y += fmaxf(h0.y + e0a.y, 0.f) + fmaxf(h1.y + e1a.y, 0.f);
        acc.z += fmaxf(h0.z + e0b.x, 0.f) + fmaxf(h1.z + e1b.x, 0.f);
        acc.w += fmaxf(h0.w + e0b.y, 0.f) + fmaxf(h1.w + e1b.y, 0.f);
    }
    if (i < end) {
        int s0 = g_srcs[i];
        uint2 u0 = __ldcs(&ea16[(size_t)i * 32 + lane]);
        float4 h0 = hin[(size_t)s0 * 32 + lane];
        float2 e0a = __half22float2(*(__half2*)&u0.x);
        float2 e0b = __half22float2(*(__half2*)&u0.y);
        acc.x += fmaxf(h0.x + e0a.x, 0.f);
        acc.y += fmaxf(h0.y + e0a.y, 0.f);
        acc.z += fmaxf(h0.z + e0b.x, 0.f);
        acc.w += fmaxf(h0.w + e0b.y, 0.f);
    }
    float el = 1.f + __ldg(eps + l);
    float4 hn = hin[(size_t)node * 32 + lane];
    float zx = el * hn.x + acc.x;
    float zy = el * hn.y + acc.y;
    float zz = el * hn.z + acc.z;
    float zw = el * hn.w + acc.w;
    size_t o = (size_t)node * DDIM + lane * 4;
    uint32_t h01, l01, h23, l23;
    split2(zx, zy, h01, l01);
    split2(zz, zw, h23, l23);
    *(uint32_t*)(g_Ahi + o)     = h01;
    *(uint32_t*)(g_Ahi + o + 2) = h23;
    *(uint32_t*)(g_Alo + o)     = l01;
    *(uint32_t*)(g_Alo + o + 2) = l23;
}

// ---------------- fused MLP: pass-outer MMA order (breaks RAW chains) ------
// For each pass, consecutive MMAs target DIFFERENT accumulators (ntl cycles
// 0..7), so the MMA stream pipelines at dispatch rate instead of stalling
// ~28 cyc on the same-d RAW dependency every instruction.
__device__ __forceinline__ void gemm_tile16(const __nv_bfloat16* __restrict__ sA_hi,
                                            const __nv_bfloat16* __restrict__ sA_lo,
                                            const uint2* __restrict__ gWf,
                                            float* acc, int lane, int mrow, int ntbase) {
    int r0 = mrow + (lane >> 2);
    int cb = (lane & 3) * 2;
#pragma unroll
    for (int pass = 0; pass < 3; pass++) {
        const __nv_bfloat16* sA = (pass == 1) ? sA_lo : sA_hi;
        int whalf = (pass == 2) ? 1 : 0;   // uint2 index: 0=(b0h,b1h), 1=(b0l,b1l)
#pragma unroll
        for (int kk = 0; kk < 8; kk++) {
            int c = kk * 16 + cb;
            uint32_t a0 = lds_u32(&sA[r0 * PA + c]);
            uint32_t a1 = lds_u32(&sA[(r0 + 8) * PA + c]);
            uint32_t a2 = lds_u32(&sA[r0 * PA + c + 8]);
            uint32_t a3 = lds_u32(&sA[(r0 + 8) * PA + c + 8]);
#pragma unroll
            for (int ntl = 0; ntl < 8; ntl++) {
                uint2 w = __ldg(&gWf[(((ntbase + ntl) * 8 + kk) * 32 + lane) * 2 + whalf]);
                float* d = acc + ntl * 4;
                MMA16816(d[0], d[1], d[2], d[3], a0, a1, a2, a3, w.x, w.y);
            }
        }
    }
}

__global__ void __launch_bounds__(512, 2)
k_mlp(int l, const float* __restrict__ x, const float* __restrict__ masks,
      const float* __restrict__ b1g, const float* __restrict__ b2g, int first) {
    const float* xin = first ? x : g_h;
    extern __shared__ char smem[];
    __nv_bfloat16* sAhi = (__nv_bfloat16*)smem;
    __nv_bfloat16* sAlo = sAhi + 128 * PA;
    float* sZ = (float*)smem;   // reused after GEMM2

    int tid = threadIdx.x, lane = tid & 31, warp = tid >> 5;
    int mrow = (warp & 7) * 16;
    int nh = warp >> 3;           // 0 or 1 (column half)
    int ntbase = nh * 8;
    int base = blockIdx.x * 128;
    int rows = min(128, NN - base);

    // load A (z hi/lo planes), zero-fill OOB rows
    for (int i = tid; i < 128 * 64; i += 512) {
        int r = i >> 6, c2 = i & 63;
        uint32_t vh = 0, vl = 0;
        if (r < rows) {
            size_t gi = (size_t)(base + r) * 64 + c2;
            vh = ((const uint32_t*)g_Ahi)[gi];
            vl = ((const uint32_t*)g_Alo)[gi];
        }
        *(uint32_t*)(sAhi + r * PA + c2 * 2) = vh;
        *(uint32_t*)(sAlo + r * PA + c2 * 2) = vl;
    }
    __syncthreads();

    const uint2* gW1 = (const uint2*)(g_Wfrag + (size_t)(l * 2) * 16384);
    const uint2* gW2 = (const uint2*)(g_Wfrag + (size_t)(l * 2 + 1) * 16384);

    float acc[32];
#pragma unroll
    for (int i = 0; i < 32; i++) acc[i] = 0.f;
    gemm_tile16(sAhi, sAlo, gW1, acc, lane, mrow, ntbase);

    // row-sharing warps (w and w+8) must BOTH finish reading sA before epi-1
    __syncthreads();

    // epilogue 1: relu(acc + b1) -> hi/lo back into sA (warp's 16r x 64c block)
    int r0 = mrow + (lane >> 2);
    int cb = (lane & 3) * 2;
#pragma unroll
    for (int ntl = 0; ntl < 8; ntl++) {
        int c = nh * 64 + ntl * 8 + cb;
        float bb0 = __ldg(b1g + l * 128 + c);
        float bb1 = __ldg(b1g + l * 128 + c + 1);
        float v00 = fmaxf(acc[ntl * 4 + 0] + bb0, 0.f);
        float v01 = fmaxf(acc[ntl * 4 + 1] + bb1, 0.f);
        float v10 = fmaxf(acc[ntl * 4 + 2] + bb0, 0.f);
        float v11 = fmaxf(acc[ntl * 4 + 3] + bb1, 0.f);
        uint32_t h0, l0, h1, l1;
        split2(v00, v01, h0, l0);
        split2(v10, v11, h1, l1);
        *(uint32_t*)&sAhi[r0 * PA + c] = h0;
        *(uint32_t*)&sAlo[r0 * PA + c] = l0;
        *(uint32_t*)&sAhi[(r0 + 8) * PA + c] = h1;
        *(uint32_t*)&sAlo[(r0 + 8) * PA + c] = l1;
        acc[ntl * 4 + 0] = 0.f; acc[ntl * 4 + 1] = 0.f;
        acc[ntl * 4 + 2] = 0.f; acc[ntl * 4 + 3] = 0.f;
    }
    __syncthreads();   // gemm2 reads cols written by the other column-half warp

    gemm_tile16(sAhi, sAlo, gW2, acc, lane, mrow, ntbase);
    __syncthreads();   // all warps done reading sA before sZ overwrite

    // epilogue 2: z = mask * (acc + b2) + x_in
    bool ok0 = (base + r0) < NN;
    bool ok1 = (base + r0 + 8) < NN;
    float m0 = ok0 ? __ldg(masks + (size_t)l * NN + base + r0) : 0.f;
    float m1 = ok1 ? __ldg(masks + (size_t)l * NN + base + r0 + 8) : 0.f;
#pragma unroll
    for (int ntl = 0; ntl < 8; ntl++) {
        int c = nh * 64 + ntl * 8 + cb;
        float bb0 = __ldg(b2g + l * 128 + c);
        float bb1 = __ldg(b2g + l * 128 + c + 1);
        float2 x0 = ok0 ? *(const float2*)(xin + (size_t)(base + r0) * 128 + c)
                        : make_float2(0.f, 0.f);
        float2 x1 = ok1 ? *(const float2*)(xin + (size_t)(base + r0 + 8) * 128 + c)
                        : make_float2(0.f, 0.f);
        float z00 = m0 * (acc[ntl * 4 + 0] + bb0) + x0.x;
        float z01 = m0 * (acc[ntl * 4 + 1] + bb1) + x0.y;
        float z10 = m1 * (acc[ntl * 4 + 2] + bb0) + x1.x;
        float z11 = m1 * (acc[ntl * 4 + 3] + bb1) + x1.y;
        *(float2*)&sZ[r0 * 128 + c] = make_float2(z00, z01);
        *(float2*)&sZ[(r0 + 8) * 128 + c] = make_float2(z10, z11);
    }
    __syncthreads();

    // BN column partials over valid rows (4 quarters of 32 rows)
    {
        int c = tid & 127, q4 = tid >> 7;
        int rbeg = q4 * 32;
        int rend = min(rbeg + 32, rows);
        float s = 0.f, q = 0.f;
        for (int r = rbeg; r < rend; ++r) {
            float v = sZ[r * 128 + c];
            s += v; q += v * v;
        }
        atomicAdd(&g_bsum[l][c], s);
        atomicAdd(&g_bsq[l][c], q);
    }
    // write z tile
    for (int i = tid; i < rows * 32; i += 512) {
        int r = i >> 5, c4 = i & 31;
        ((float4*)(g_z + (size_t)(base + r) * 128))[c4] = ((const float4*)(sZ + r * 128))[c4];
    }
}

// ---------------- BN finalize + apply + relu ----------------
__global__ void k_bn_apply(int l, float* __restrict__ outp,
                           const float* __restrict__ gamma,
                           const float* __restrict__ beta, int last) {
    int idx = blockIdx.x * blockDim.x + threadIdx.x;
    if (idx >= NN * 32) return;
    float* o = last ? outp : g_h;
    int c4 = idx & 31;
    int c = c4 * 4;
    float4 z = ((const float4*)g_z)[idx];
    float invN = 1.f / (float)NN;
    float4 r;
    {
        float mu = g_bsum[l][c + 0] * invN;
        float var = g_bsq[l][c + 0] * invN - mu * mu;
        r.x = fmaxf(__ldg(gamma + l * 128 + c + 0) * (z.x - mu) * rsqrtf(var + BN_EPS) + __ldg(beta + l * 128 + c + 0), 0.f);
    }
    {
        float mu = g_bsum[l][c + 1] * invN;
        float var = g_bsq[l][c + 1] * invN - mu * mu;
        r.y = fmaxf(__ldg(gamma + l * 128 + c + 1) * (z.y - mu) * rsqrtf(var + BN_EPS) + __ldg(beta + l * 128 + c + 1), 0.f);
    }
    {
        float mu = g_bsum[l][c + 2] * invN;
        float var = g_bsq[l][c + 2] * invN - mu * mu;
        r.z = fmaxf(__ldg(gamma + l * 128 + c + 2) * (z.z - mu) * rsqrtf(var + BN_EPS) + __ldg(beta + l * 128 + c + 2), 0.f);
    }
    {
        float mu = g_bsum[l][c + 3] * invN;
        float var = g_bsq[l][c + 3] * invN - mu * mu;
        r.w = fmaxf(__ldg(gamma + l * 128 + c + 3) * (z.w - mu) * rsqrtf(var + BN_EPS) + __ldg(beta + l * 128 + c + 3), 0.f);
    }
    ((float4*)o)[idx] = r;
}

// ---------------- launch ----------------
extern "C" void kernel_launch(void* const* d_in, const int* in_sizes, int n_in,
                              void* d_out, int out_size) {
    const float* x     = (const float*)d_in[0];
    const float* ea    = (const float*)d_in[1];
    const float* masks = (const float*)d_in[2];
    const int*   ei    = (const int*)d_in[3];
    const float* eps   = (const float*)d_in[4];
    const float* W1    = (const float*)d_in[5];
    const float* b1    = (const float*)d_in[6];
    const float* W2    = (const float*)d_in[7];
    const float* b2    = (const float*)d_in[8];
    const float* gamma = (const float*)d_in[9];
    const float* beta  = (const float*)d_in[10];
    float* out = (float*)d_out;

    cudaFuncSetAttribute(k_mlp, cudaFuncAttributeMaxDynamicSharedMemorySize, SMEM_BYTES);

    k_zero<<<(NN + 255) / 256, 256>>>(W1, W2);
    k_pre<<<NE / 32, 256>>>(ei, ei + NE, ea);

    for (int l = 0; l < 3; l++) {
        int first = (l == 0) ? 1 : 0;
        int last = (l == 2) ? 1 : 0;
        k_agg<<<(NN + 7) / 8, 256>>>(x, eps, l, first);
        k_mlp<<<NT, 512, SMEM_BYTES>>>(l, x, masks, b1, b2, first);
        k_bn_apply<<<(NN * 32 + 255) / 256, 256>>>(l, out, gamma, beta, last);
    }
}

// round 14
// speedup vs baseline: 1.9214x; 1.9214x over previous
#include <cuda_runtime.h>
#include <cuda_bf16.h>
#include <cuda_fp16.h>
#include <cstdint>

#define NN 100000
#define NE 1600000
#define DDIM 128
#define CAP 64                         // slot capacity per node (max deg ~45)
#define NT 782
#define BN_EPS 1e-5f
#define PA 136                         // bf16 SMEM row pitch for A planes
#define SMEM_BYTES (2 * 128 * PA * 2)  // 69632: two A planes (sZ reuses)

// ---------------- device scratch (static globals: allowed) ----------------
__device__ float g_h[(size_t)NN * DDIM];
__device__ float g_z[(size_t)NN * DDIM];
__device__ __nv_bfloat16 g_Ahi[(size_t)NN * DDIM];
__device__ __nv_bfloat16 g_Alo[(size_t)NN * DDIM];
__device__ int g_cnt[NN];
__device__ int g_srcs[(size_t)NN * CAP];
__device__ __half g_ea16[(size_t)NN * CAP * DDIM];   // slot-CSR fp16 edge_attr
__device__ uint32_t g_Wfrag[6 * 16384];  // 6 matrices, fragment-major
__device__ float g_bsum[3][DDIM];
__device__ float g_bsq[3][DDIM];

// ---------------- helpers ----------------
__device__ __forceinline__ void split2(float a, float b, uint32_t& hi, uint32_t& lo) {
    __nv_bfloat16 ah = __float2bfloat16(a), bh = __float2bfloat16(b);
    __nv_bfloat16 al = __float2bfloat16(a - __bfloat162float(ah));
    __nv_bfloat16 bl = __float2bfloat16(b - __bfloat162float(bh));
    __nv_bfloat162 H; H.x = ah; H.y = bh;
    __nv_bfloat162 L; L.x = al; L.y = bl;
    hi = *reinterpret_cast<uint32_t*>(&H);
    lo = *reinterpret_cast<uint32_t*>(&L);
}

__device__ __forceinline__ uint32_t lds_u32(const __nv_bfloat16* p) {
    return *reinterpret_cast<const uint32_t*>(p);
}

#define MMA16816(d0,d1,d2,d3,a0,a1,a2,a3,b0,b1)                               \
    asm volatile("mma.sync.aligned.m16n8k16.row.col.f32.bf16.bf16.f32 "       \
                 "{%0,%1,%2,%3},{%4,%5,%6,%7},{%8,%9},{%0,%1,%2,%3};"         \
                 : "+f"(d0), "+f"(d1), "+f"(d2), "+f"(d3)                     \
                 : "r"(a0), "r"(a1), "r"(a2), "r"(a3), "r"(b0), "r"(b1))

// ---------------- launch 1: W split + zero counters/BN ----------------
__global__ void k_zero(const float* __restrict__ W1, const float* __restrict__ W2) {
    int i = blockIdx.x * blockDim.x + threadIdx.x;
    if (i < 6 * 16384) {
        int part = i & 3;              // 0=b0h 1=b1h 2=b0l 3=b1l
        int lane = (i >> 2) & 31;
        int fragid = (i >> 7) & 127;   // nt*8 + kk
        int mat = i >> 14;             // l*2 + j
        int l = mat >> 1, j = mat & 1;
        int nt = fragid >> 3, kk = fragid & 7;
        int bn = nt * 8 + (lane >> 2);
        int bk = kk * 16 + (lane & 3) * 2 + (part & 1) * 8;
        const float* Wsrc = (j ? W2 : W1) + (size_t)l * 16384;
        float w0 = Wsrc[bk * 128 + bn];
        float w1 = Wsrc[(bk + 1) * 128 + bn];
        uint32_t hi, lo;
        split2(w0, w1, hi, lo);
        g_Wfrag[i] = (part >= 2) ? lo : hi;
    }
    if (i < NN) g_cnt[i] = 0;
    if (i < 3 * DDIM) {
        ((float*)g_bsum)[i] = 0.f;
        ((float*)g_bsq)[i] = 0.f;
    }
}

// ---------------- launch 2: slot scatter + fp16 convert ----------------
__global__ void k_pre(const int* __restrict__ src, const int* __restrict__ dst,
                      const float* __restrict__ ea) {
    int gwarp = (blockIdx.x * 256 + threadIdx.x) >> 5;
    int lane = threadIdx.x & 31;
    int ebase = gwarp * 4;
    if (ebase >= NE) return;
    int pos = -1, s = 0;
    if (lane < 4 && ebase + lane < NE) {
        int e = ebase + lane;
        int d = __ldg(dst + e);
        int r = atomicAdd(&g_cnt[d], 1);
        if (r < CAP) pos = d * CAP + r;
        s = __ldg(src + e);
    }
    const float4* ea4 = (const float4*)ea;
#pragma unroll
    for (int k = 0; k < 4; k++) {
        int e = ebase + k;
        if (e >= NE) break;
        int p = __shfl_sync(0xffffffff, pos, k);
        if (p < 0) continue;
        if (lane == k) g_srcs[p] = s;
        float4 v = ea4[(size_t)e * 32 + lane];
        __half2 a = __float22half2_rn(make_float2(v.x, v.y));
        __half2 b = __float22half2_rn(make_float2(v.z, v.w));
        uint2 u;
        u.x = *reinterpret_cast<uint32_t*>(&a);
        u.y = *reinterpret_cast<uint32_t*>(&b);
        ((uint2*)g_ea16)[(size_t)p * 32 + lane] = u;
    }
}

// ---------------- aggregation: warp per node, 2x unrolled (round-8) --------
__global__ void k_agg(const float* __restrict__ x, const float* __restrict__ eps,
                      int l, int first) {
    int node = (blockIdx.x * blockDim.x + threadIdx.x) >> 5;
    if (node >= NN) return;
    int lane = threadIdx.x & 31;
    int beg = node * CAP;
    int end = beg + min(g_cnt[node], CAP);
    const float4* hin = (const float4*)(first ? x : g_h);
    const uint2* ea16 = (const uint2*)g_ea16;
    float4 acc = make_float4(0.f, 0.f, 0.f, 0.f);
    int i = beg;
    for (; i + 2 <= end; i += 2) {
        int s0 = g_srcs[i], s1 = g_srcs[i + 1];
        uint2 u0 = __ldcs(&ea16[(size_t)i * 32 + lane]);
        uint2 u1 = __ldcs(&ea16[(size_t)(i + 1) * 32 + lane]);
        float4 h0 = hin[(size_t)s0 * 32 + lane];
        float4 h1 = hin[(size_t)s1 * 32 + lane];
        float2 e0a = __half22float2(*(__half2*)&u0.x);
        float2 e0b = __half22float2(*(__half2*)&u0.y);
        float2 e1a = __half22float2(*(__half2*)&u1.x);
        float2 e1b = __half22float2(*(__half2*)&u1.y);
        acc.x += fmaxf(h0.x + e0a.x, 0.f) + fmaxf(h1.x + e1a.x, 0.f);
        acc.y += fmaxf(h0.y + e0a.y, 0.f) + fmaxf(h1.y + e1a.y, 0.f);
        acc.z += fmaxf(h0.z + e0b.x, 0.f) + fmaxf(h1.z + e1b.x, 0.f);
        acc.w += fmaxf(h0.w + e0b.y, 0.f) + fmaxf(h1.w + e1b.y, 0.f);
    }
    if (i < end) {
        int s0 = g_srcs[i];
        uint2 u0 = __ldcs(&ea16[(size_t)i * 32 + lane]);
        float4 h0 = hin[(size_t)s0 * 32 + lane];
        float2 e0a = __half22float2(*(__half2*)&u0.x);
        float2 e0b = __half22float2(*(__half2*)&u0.y);
        acc.x += fmaxf(h0.x + e0a.x, 0.f);
        acc.y += fmaxf(h0.y + e0a.y, 0.f);
        acc.z += fmaxf(h0.z + e0b.x, 0.f);
        acc.w += fmaxf(h0.w + e0b.y, 0.f);
    }
    float el = 1.f + __ldg(eps + l);
    float4 hn = hin[(size_t)node * 32 + lane];
    float zx = el * hn.x + acc.x;
    float zy = el * hn.y + acc.y;
    float zz = el * hn.z + acc.z;
    float zw = el * hn.w + acc.w;
    size_t o = (size_t)node * DDIM + lane * 4;
    uint32_t h01, l01, h23, l23;
    split2(zx, zy, h01, l01);
    split2(zz, zw, h23, l23);
    *(uint32_t*)(g_Ahi + o)     = h01;
    *(uint32_t*)(g_Ahi + o + 2) = h23;
    *(uint32_t*)(g_Alo + o)     = l01;
    *(uint32_t*)(g_Alo + o + 2) = l23;
}

// ---------------- fused MLP: round-8 structure + 2-way ntl interleave ------
// Same loads/bytes as round-8 (uint4 W per ntl, kk-outer). The only change:
// ntl processed in PAIRS with the 6 MMAs interleaved across the two
// accumulator sets, raising same-accumulator RAW distance 1 -> 2.
__device__ __forceinline__ void gemm_tile16(const __nv_bfloat16* __restrict__ sA_hi,
                                            const __nv_bfloat16* __restrict__ sA_lo,
                                            const uint4* __restrict__ gWf,
                                            float* acc, int lane, int mrow, int ntbase) {
    int r0 = mrow + (lane >> 2);
    int cb = (lane & 3) * 2;
#pragma unroll
    for (int kk = 0; kk < 8; kk++) {
        int c = kk * 16 + cb;
        uint32_t a0 = lds_u32(&sA_hi[r0 * PA + c]);
        uint32_t a1 = lds_u32(&sA_hi[(r0 + 8) * PA + c]);
        uint32_t a2 = lds_u32(&sA_hi[r0 * PA + c + 8]);
        uint32_t a3 = lds_u32(&sA_hi[(r0 + 8) * PA + c + 8]);
        uint32_t l0 = lds_u32(&sA_lo[r0 * PA + c]);
        uint32_t l1 = lds_u32(&sA_lo[(r0 + 8) * PA + c]);
        uint32_t l2 = lds_u32(&sA_lo[r0 * PA + c + 8]);
        uint32_t l3 = lds_u32(&sA_lo[(r0 + 8) * PA + c + 8]);
#pragma unroll
        for (int ntl = 0; ntl < 8; ntl += 2) {
            uint4 w0 = __ldg(&gWf[((ntbase + ntl) * 8 + kk) * 32 + lane]);
            uint4 w1 = __ldg(&gWf[((ntbase + ntl + 1) * 8 + kk) * 32 + lane]);
            float* d0 = acc + ntl * 4;
            float* d1 = acc + (ntl + 1) * 4;
            MMA16816(d0[0], d0[1], d0[2], d0[3], a0, a1, a2, a3, w0.x, w0.y);
            MMA16816(d1[0], d1[1], d1[2], d1[3], a0, a1, a2, a3, w1.x, w1.y);
            MMA16816(d0[0], d0[1], d0[2], d0[3], l0, l1, l2, l3, w0.x, w0.y);
            MMA16816(d1[0], d1[1], d1[2], d1[3], l0, l1, l2, l3, w1.x, w1.y);
            MMA16816(d0[0], d0[1], d0[2], d0[3], a0, a1, a2, a3, w0.z, w0.w);
            MMA16816(d1[0], d1[1], d1[2], d1[3], a0, a1, a2, a3, w1.z, w1.w);
        }
    }
}

__global__ void __launch_bounds__(512, 2)
k_mlp(int l, const float* __restrict__ x, const float* __restrict__ masks,
      const float* __restrict__ b1g, const float* __restrict__ b2g, int first) {
    const float* xin = first ? x : g_h;
    extern __shared__ char smem[];
    __nv_bfloat16* sAhi = (__nv_bfloat16*)smem;
    __nv_bfloat16* sAlo = sAhi + 128 * PA;
    float* sZ = (float*)smem;   // reused after GEMM2

    int tid = threadIdx.x, lane = tid & 31, warp = tid >> 5;
    int mrow = (warp & 7) * 16;
    int nh = warp >> 3;           // 0 or 1 (column half)
    int ntbase = nh * 8;
    int base = blockIdx.x * 128;
    int rows = min(128, NN - base);

    // load A (z hi/lo planes), zero-fill OOB rows
    for (int i = tid; i < 128 * 64; i += 512) {
        int r = i >> 6, c2 = i & 63;
        uint32_t vh = 0, vl = 0;
        if (r < rows) {
            size_t gi = (size_t)(base + r) * 64 + c2;
            vh = ((const uint32_t*)g_Ahi)[gi];
            vl = ((const uint32_t*)g_Alo)[gi];
        }
        *(uint32_t*)(sAhi + r * PA + c2 * 2) = vh;
        *(uint32_t*)(sAlo + r * PA + c2 * 2) = vl;
    }
    __syncthreads();

    const uint4* gW1 = (const uint4*)(g_Wfrag + (size_t)(l * 2) * 16384);
    const uint4* gW2 = (const uint4*)(g_Wfrag + (size_t)(l * 2 + 1) * 16384);

    float acc[32];
#pragma unroll
    for (int i = 0; i < 32; i++) acc[i] = 0.f;
    gemm_tile16(sAhi, sAlo, gW1, acc, lane, mrow, ntbase);

    // row-sharing warps (w and w+8) must BOTH finish reading sA before epi-1
    __syncthreads();

    // epilogue 1: relu(acc + b1) -> hi/lo back into sA (warp's 16r x 64c block)
    int r0 = mrow + (lane >> 2);
    int cb = (lane & 3) * 2;
#pragma unroll
    for (int ntl = 0; ntl < 8; ntl++) {
        int c = nh * 64 + ntl * 8 + cb;
        float bb0 = __ldg(b1g + l * 128 + c);
        float bb1 = __ldg(b1g + l * 128 + c + 1);
        float v00 = fmaxf(acc[ntl * 4 + 0] + bb0, 0.f);
        float v01 = fmaxf(acc[ntl * 4 + 1] + bb1, 0.f);
        float v10 = fmaxf(acc[ntl * 4 + 2] + bb0, 0.f);
        float v11 = fmaxf(acc[ntl * 4 + 3] + bb1, 0.f);
        uint32_t h0, l0, h1, l1;
        split2(v00, v01, h0, l0);
        split2(v10, v11, h1, l1);
        *(uint32_t*)&sAhi[r0 * PA + c] = h0;
        *(uint32_t*)&sAlo[r0 * PA + c] = l0;
        *(uint32_t*)&sAhi[(r0 + 8) * PA + c] = h1;
        *(uint32_t*)&sAlo[(r0 + 8) * PA + c] = l1;
        acc[ntl * 4 + 0] = 0.f; acc[ntl * 4 + 1] = 0.f;
        acc[ntl * 4 + 2] = 0.f; acc[ntl * 4 + 3] = 0.f;
    }
    __syncthreads();   // gemm2 reads cols written by the other column-half warp

    gemm_tile16(sAhi, sAlo, gW2, acc, lane, mrow, ntbase);
    __syncthreads();   // all warps done reading sA before sZ overwrite

    // epilogue 2: z = mask * (acc + b2) + x_in
    bool ok0 = (base + r0) < NN;
    bool ok1 = (base + r0 + 8) < NN;
    float m0 = ok0 ? __ldg(masks + (size_t)l * NN + base + r0) : 0.f;
    float m1 = ok1 ? __ldg(masks + (size_t)l * NN + base + r0 + 8) : 0.f;
#pragma unroll
    for (int ntl = 0; ntl < 8; ntl++) {
        int c = nh * 64 + ntl * 8 + cb;
        float bb0 = __ldg(b2g + l * 128 + c);
        float bb1 = __ldg(b2g + l * 128 + c + 1);
        float2 x0 = ok0 ? *(const float2*)(xin + (size_t)(base + r0) * 128 + c)
                        : make_float2(0.f, 0.f);
        float2 x1 = ok1 ? *(const float2*)(xin + (size_t)(base + r0 + 8) * 128 + c)
                        : make_float2(0.f, 0.f);
        float z00 = m0 * (acc[ntl * 4 + 0] + bb0) + x0.x;
        float z01 = m0 * (acc[ntl * 4 + 1] + bb1) + x0.y;
        float z10 = m1 * (acc[ntl * 4 + 2] + bb0) + x1.x;
        float z11 = m1 * (acc[ntl * 4 + 3] + bb1) + x1.y;
        *(float2*)&sZ[r0 * 128 + c] = make_float2(z00, z01);
        *(float2*)&sZ[(r0 + 8) * 128 + c] = make_float2(z10, z11);
    }
    __syncthreads();

    // BN column partials over valid rows (4 quarters of 32 rows)
    {
        int c = tid & 127, q4 = tid >> 7;
        int rbeg = q4 * 32;
        int rend = min(rbeg + 32, rows);
        float s = 0.f, q = 0.f;
        for (int r = rbeg; r < rend; ++r) {
            float v = sZ[r * 128 + c];
            s += v; q += v * v;
        }
        atomicAdd(&g_bsum[l][c], s);
        atomicAdd(&g_bsq[l][c], q);
    }
    // write z tile
    for (int i = tid; i < rows * 32; i += 512) {
        int r = i >> 5, c4 = i & 31;
        ((float4*)(g_z + (size_t)(base + r) * 128))[c4] = ((const float4*)(sZ + r * 128))[c4];
    }
}

// ---------------- BN finalize + apply + relu ----------------
__global__ void k_bn_apply(int l, float* __restrict__ outp,
                           const float* __restrict__ gamma,
                           const float* __restrict__ beta, int last) {
    int idx = blockIdx.x * blockDim.x + threadIdx.x;
    if (idx >= NN * 32) return;
    float* o = last ? outp : g_h;
    int c4 = idx & 31;
    int c = c4 * 4;
    float4 z = ((const float4*)g_z)[idx];
    float invN = 1.f / (float)NN;
    float4 r;
    {
        float mu = g_bsum[l][c + 0] * invN;
        float var = g_bsq[l][c + 0] * invN - mu * mu;
        r.x = fmaxf(__ldg(gamma + l * 128 + c + 0) * (z.x - mu) * rsqrtf(var + BN_EPS) + __ldg(beta + l * 128 + c + 0), 0.f);
    }
    {
        float mu = g_bsum[l][c + 1] * invN;
        float var = g_bsq[l][c + 1] * invN - mu * mu;
        r.y = fmaxf(__ldg(gamma + l * 128 + c + 1) * (z.y - mu) * rsqrtf(var + BN_EPS) + __ldg(beta + l * 128 + c + 1), 0.f);
    }
    {
        float mu = g_bsum[l][c + 2] * invN;
        float var = g_bsq[l][c + 2] * invN - mu * mu;
        r.z = fmaxf(__ldg(gamma + l * 128 + c + 2) * (z.z - mu) * rsqrtf(var + BN_EPS) + __ldg(beta + l * 128 + c + 2), 0.f);
    }
    {
        float mu = g_bsum[l][c + 3] * invN;
        float var = g_bsq[l][c + 3] * invN - mu * mu;
        r.w = fmaxf(__ldg(gamma + l * 128 + c + 3) * (z.w - mu) * rsqrtf(var + BN_EPS) + __ldg(beta + l * 128 + c + 3), 0.f);
    }
    ((float4*)o)[idx] = r;
}

// ---------------- launch ----------------
extern "C" void kernel_launch(void* const* d_in, const int* in_sizes, int n_in,
                              void* d_out, int out_size) {
    const float* x     = (const float*)d_in[0];
    const float* ea    = (const float*)d_in[1];
    const float* masks = (const float*)d_in[2];
    const int*   ei    = (const int*)d_in[3];
    const float* eps   = (const float*)d_in[4];
    const float* W1    = (const float*)d_in[5];
    const float* b1    = (const float*)d_in[6];
    const float* W2    = (const float*)d_in[7];
    const float* b2    = (const float*)d_in[8];
    const float* gamma = (const float*)d_in[9];
    const float* beta  = (const float*)d_in[10];
    float* out = (float*)d_out;

    cudaFuncSetAttribute(k_mlp, cudaFuncAttributeMaxDynamicSharedMemorySize, SMEM_BYTES);

    k_zero<<<(NN + 255) / 256, 256>>>(W1, W2);
    k_pre<<<NE / 32, 256>>>(ei, ei + NE, ea);

    for (int l = 0; l < 3; l++) {
        int first = (l == 0) ? 1 : 0;
        int last = (l == 2) ? 1 : 0;
        k_agg<<<(NN + 7) / 8, 256>>>(x, eps, l, first);
        k_mlp<<<NT, 512, SMEM_BYTES>>>(l, x, masks, b1, b2, first);
        k_bn_apply<<<(NN * 32 + 255) / 256, 256>>>(l, out, gamma, beta, last);
    }
}

// round 15
// speedup vs baseline: 2.0654x; 1.0750x over previous
#include <cuda_runtime.h>
#include <cuda_bf16.h>
#include <cuda_fp16.h>
#include <cstdint>

#define NN 100000
#define NE 1600000
#define DDIM 128
#define CAP 64                         // slot capacity per node (max deg ~45)
#define NT 782
#define BN_EPS 1e-5f
#define PA 136                         // bf16 SMEM row pitch for A planes
#define SMEM_BYTES (2 * 128 * PA * 2)  // 69632: two A planes (sZ reuses)

// ---------------- device scratch (static globals: allowed) ----------------
__device__ float g_h[(size_t)NN * DDIM];
__device__ float g_z[(size_t)NN * DDIM];
__device__ __nv_bfloat16 g_Ahi[(size_t)NN * DDIM];
__device__ __nv_bfloat16 g_Alo[(size_t)NN * DDIM];
__device__ int g_cnt[NN];
__device__ int2 g_se[(size_t)NN * CAP];              // (src, eid) per slot
__device__ __half g_ea16[(size_t)NN * CAP * DDIM];   // slot-CSR fp16 edge_attr
__device__ uint32_t g_Wfrag[6 * 16384];  // 6 matrices, fragment-major
__device__ float g_bsum[3][DDIM];
__device__ float g_bsq[3][DDIM];

// ---------------- helpers ----------------
__device__ __forceinline__ void split2(float a, float b, uint32_t& hi, uint32_t& lo) {
    __nv_bfloat16 ah = __float2bfloat16(a), bh = __float2bfloat16(b);
    __nv_bfloat16 al = __float2bfloat16(a - __bfloat162float(ah));
    __nv_bfloat16 bl = __float2bfloat16(b - __bfloat162float(bh));
    __nv_bfloat162 H; H.x = ah; H.y = bh;
    __nv_bfloat162 L; L.x = al; L.y = bl;
    hi = *reinterpret_cast<uint32_t*>(&H);
    lo = *reinterpret_cast<uint32_t*>(&L);
}

__device__ __forceinline__ uint32_t lds_u32(const __nv_bfloat16* p) {
    return *reinterpret_cast<const uint32_t*>(p);
}

#define MMA16816(d0,d1,d2,d3,a0,a1,a2,a3,b0,b1)                               \
    asm volatile("mma.sync.aligned.m16n8k16.row.col.f32.bf16.bf16.f32 "       \
                 "{%0,%1,%2,%3},{%4,%5,%6,%7},{%8,%9},{%0,%1,%2,%3};"         \
                 : "+f"(d0), "+f"(d1), "+f"(d2), "+f"(d3)                     \
                 : "r"(a0), "r"(a1), "r"(a2), "r"(a3), "r"(b0), "r"(b1))

// ---------------- launch 1: W split + zero counters/BN ----------------
__global__ void k_zero(const float* __restrict__ W1, const float* __restrict__ W2) {
    int i = blockIdx.x * blockDim.x + threadIdx.x;
    if (i < 6 * 16384) {
        int part = i & 3;              // 0=b0h 1=b1h 2=b0l 3=b1l
        int lane = (i >> 2) & 31;
        int fragid = (i >> 7) & 127;   // nt*8 + kk
        int mat = i >> 14;             // l*2 + j
        int l = mat >> 1, j = mat & 1;
        int nt = fragid >> 3, kk = fragid & 7;
        int bn = nt * 8 + (lane >> 2);
        int bk = kk * 16 + (lane & 3) * 2 + (part & 1) * 8;
        const float* Wsrc = (j ? W2 : W1) + (size_t)l * 16384;
        float w0 = Wsrc[bk * 128 + bn];
        float w1 = Wsrc[(bk + 1) * 128 + bn];
        uint32_t hi, lo;
        split2(w0, w1, hi, lo);
        g_Wfrag[i] = (part >= 2) ? lo : hi;
    }
    if (i < NN) g_cnt[i] = 0;
    if (i < 3 * DDIM) {
        ((float*)g_bsum)[i] = 0.f;
        ((float*)g_bsq)[i] = 0.f;
    }
}

// ---------------- launch 2: index-only slot scatter ----------------
__global__ void k_scat(const int* __restrict__ src, const int* __restrict__ dst) {
    int e = blockIdx.x * blockDim.x + threadIdx.x;
    if (e >= NE) return;
    int d = __ldg(dst + e);
    int r = atomicAdd(&g_cnt[d], 1);
    if (r < CAP) g_se[d * CAP + r] = make_int2(__ldg(src + e), e);
}

// ---------------- aggregation: warp per node over slots --------------------
// layer 0: gathers fp32 ea by eid (exact messages) AND emits the fp16 slot
// stream for layers 1,2 — replaces the separate conversion pass.
__global__ void k_agg(const float* __restrict__ x, const float* __restrict__ ea,
                      const float* __restrict__ eps, int l, int first) {
    int node = (blockIdx.x * blockDim.x + threadIdx.x) >> 5;
    if (node >= NN) return;
    int lane = threadIdx.x & 31;
    int beg = node * CAP;
    int end = beg + min(g_cnt[node], CAP);
    const float4* hin = (const float4*)(first ? x : g_h);
    float4 acc = make_float4(0.f, 0.f, 0.f, 0.f);

    if (first) {
        const float4* ea4 = (const float4*)ea;
        uint2* ea16 = (uint2*)g_ea16;
        int i = beg;
        for (; i + 2 <= end; i += 2) {
            int2 a = g_se[i];
            int2 b = g_se[i + 1];
            float4 e0 = __ldcs(&ea4[(size_t)a.y * 32 + lane]);
            float4 e1 = __ldcs(&ea4[(size_t)b.y * 32 + lane]);
            float4 h0 = hin[(size_t)a.x * 32 + lane];
            float4 h1 = hin[(size_t)b.x * 32 + lane];
            acc.x += fmaxf(h0.x + e0.x, 0.f) + fmaxf(h1.x + e1.x, 0.f);
            acc.y += fmaxf(h0.y + e0.y, 0.f) + fmaxf(h1.y + e1.y, 0.f);
            acc.z += fmaxf(h0.z + e0.z, 0.f) + fmaxf(h1.z + e1.z, 0.f);
            acc.w += fmaxf(h0.w + e0.w, 0.f) + fmaxf(h1.w + e1.w, 0.f);
            __half2 p0a = __float22half2_rn(make_float2(e0.x, e0.y));
            __half2 p0b = __float22half2_rn(make_float2(e0.z, e0.w));
            __half2 p1a = __float22half2_rn(make_float2(e1.x, e1.y));
            __half2 p1b = __float22half2_rn(make_float2(e1.z, e1.w));
            uint2 u0, u1;
            u0.x = *(uint32_t*)&p0a; u0.y = *(uint32_t*)&p0b;
            u1.x = *(uint32_t*)&p1a; u1.y = *(uint32_t*)&p1b;
            __stcs(&ea16[(size_t)i * 32 + lane], u0);
            __stcs(&ea16[(size_t)(i + 1) * 32 + lane], u1);
        }
        if (i < end) {
            int2 a = g_se[i];
            float4 e0 = __ldcs(&ea4[(size_t)a.y * 32 + lane]);
            float4 h0 = hin[(size_t)a.x * 32 + lane];
            acc.x += fmaxf(h0.x + e0.x, 0.f);
            acc.y += fmaxf(h0.y + e0.y, 0.f);
            acc.z += fmaxf(h0.z + e0.z, 0.f);
            acc.w += fmaxf(h0.w + e0.w, 0.f);
            __half2 p0a = __float22half2_rn(make_float2(e0.x, e0.y));
            __half2 p0b = __float22half2_rn(make_float2(e0.z, e0.w));
            uint2 u0;
            u0.x = *(uint32_t*)&p0a; u0.y = *(uint32_t*)&p0b;
            __stcs(&ea16[(size_t)i * 32 + lane], u0);
        }
    } else {
        const uint2* ea16 = (const uint2*)g_ea16;
        int i = beg;
        for (; i + 2 <= end; i += 2) {
            int s0 = g_se[i].x, s1 = g_se[i + 1].x;
            uint2 u0 = __ldcs(&ea16[(size_t)i * 32 + lane]);
            uint2 u1 = __ldcs(&ea16[(size_t)(i + 1) * 32 + lane]);
            float4 h0 = hin[(size_t)s0 * 32 + lane];
            float4 h1 = hin[(size_t)s1 * 32 + lane];
            float2 e0a = __half22float2(*(__half2*)&u0.x);
            float2 e0b = __half22float2(*(__half2*)&u0.y);
            float2 e1a = __half22float2(*(__half2*)&u1.x);
            float2 e1b = __half22float2(*(__half2*)&u1.y);
            acc.x += fmaxf(h0.x + e0a.x, 0.f) + fmaxf(h1.x + e1a.x, 0.f);
            acc.y += fmaxf(h0.y + e0a.y, 0.f) + fmaxf(h1.y + e1a.y, 0.f);
            acc.z += fmaxf(h0.z + e0b.x, 0.f) + fmaxf(h1.z + e1b.x, 0.f);
            acc.w += fmaxf(h0.w + e0b.y, 0.f) + fmaxf(h1.w + e1b.y, 0.f);
        }
        if (i < end) {
            int s0 = g_se[i].x;
            uint2 u0 = __ldcs(&ea16[(size_t)i * 32 + lane]);
            float4 h0 = hin[(size_t)s0 * 32 + lane];
            float2 e0a = __half22float2(*(__half2*)&u0.x);
            float2 e0b = __half22float2(*(__half2*)&u0.y);
            acc.x += fmaxf(h0.x + e0a.x, 0.f);
            acc.y += fmaxf(h0.y + e0a.y, 0.f);
            acc.z += fmaxf(h0.z + e0b.x, 0.f);
            acc.w += fmaxf(h0.w + e0b.y, 0.f);
        }
    }

    float el = 1.f + __ldg(eps + l);
    float4 hn = hin[(size_t)node * 32 + lane];
    float zx = el * hn.x + acc.x;
    float zy = el * hn.y + acc.y;
    float zz = el * hn.z + acc.z;
    float zw = el * hn.w + acc.w;
    size_t o = (size_t)node * DDIM + lane * 4;
    uint32_t h01, l01, h23, l23;
    split2(zx, zy, h01, l01);
    split2(zz, zw, h23, l23);
    *(uint32_t*)(g_Ahi + o)     = h01;
    *(uint32_t*)(g_Ahi + o + 2) = h23;
    *(uint32_t*)(g_Alo + o)     = l01;
    *(uint32_t*)(g_Alo + o + 2) = l23;
}

// ---------------- fused MLP: round-8 structure (110us accepted floor) ------
__device__ __forceinline__ void gemm_tile16(const __nv_bfloat16* __restrict__ sA_hi,
                                            const __nv_bfloat16* __restrict__ sA_lo,
                                            const uint4* __restrict__ gWf,
                                            float* acc, int lane, int mrow, int ntbase) {
    int r0 = mrow + (lane >> 2);
    int cb = (lane & 3) * 2;
#pragma unroll
    for (int kk = 0; kk < 8; kk++) {
        int c = kk * 16 + cb;
        uint32_t a0 = lds_u32(&sA_hi[r0 * PA + c]);
        uint32_t a1 = lds_u32(&sA_hi[(r0 + 8) * PA + c]);
        uint32_t a2 = lds_u32(&sA_hi[r0 * PA + c + 8]);
        uint32_t a3 = lds_u32(&sA_hi[(r0 + 8) * PA + c + 8]);
        uint32_t l0 = lds_u32(&sA_lo[r0 * PA + c]);
        uint32_t l1 = lds_u32(&sA_lo[(r0 + 8) * PA + c]);
        uint32_t l2 = lds_u32(&sA_lo[r0 * PA + c + 8]);
        uint32_t l3 = lds_u32(&sA_lo[(r0 + 8) * PA + c + 8]);
#pragma unroll
        for (int ntl = 0; ntl < 8; ntl++) {
            uint4 w = __ldg(&gWf[((ntbase + ntl) * 8 + kk) * 32 + lane]);
            float* d = acc + ntl * 4;
            MMA16816(d[0], d[1], d[2], d[3], a0, a1, a2, a3, w.x, w.y);
            MMA16816(d[0], d[1], d[2], d[3], l0, l1, l2, l3, w.x, w.y);
            MMA16816(d[0], d[1], d[2], d[3], a0, a1, a2, a3, w.z, w.w);
        }
    }
}

__global__ void __launch_bounds__(512, 2)
k_mlp(int l, const float* __restrict__ x, const float* __restrict__ masks,
      const float* __restrict__ b1g, const float* __restrict__ b2g, int first) {
    const float* xin = first ? x : g_h;
    extern __shared__ char smem[];
    __nv_bfloat16* sAhi = (__nv_bfloat16*)smem;
    __nv_bfloat16* sAlo = sAhi + 128 * PA;
    float* sZ = (float*)smem;   // reused after GEMM2

    int tid = threadIdx.x, lane = tid & 31, warp = tid >> 5;
    int mrow = (warp & 7) * 16;
    int nh = warp >> 3;           // 0 or 1 (column half)
    int ntbase = nh * 8;
    int base = blockIdx.x * 128;
    int rows = min(128, NN - base);

    // load A (z hi/lo planes), zero-fill OOB rows
    for (int i = tid; i < 128 * 64; i += 512) {
        int r = i >> 6, c2 = i & 63;
        uint32_t vh = 0, vl = 0;
        if (r < rows) {
            size_t gi = (size_t)(base + r) * 64 + c2;
            vh = ((const uint32_t*)g_Ahi)[gi];
            vl = ((const uint32_t*)g_Alo)[gi];
        }
        *(uint32_t*)(sAhi + r * PA + c2 * 2) = vh;
        *(uint32_t*)(sAlo + r * PA + c2 * 2) = vl;
    }
    __syncthreads();

    const uint4* gW1 = (const uint4*)(g_Wfrag + (size_t)(l * 2) * 16384);
    const uint4* gW2 = (const uint4*)(g_Wfrag + (size_t)(l * 2 + 1) * 16384);

    float acc[32];
#pragma unroll
    for (int i = 0; i < 32; i++) acc[i] = 0.f;
    gemm_tile16(sAhi, sAlo, gW1, acc, lane, mrow, ntbase);

    // row-sharing warps (w and w+8) must BOTH finish reading sA before epi-1
    __syncthreads();

    // epilogue 1: relu(acc + b1) -> hi/lo back into sA (warp's 16r x 64c block)
    int r0 = mrow + (lane >> 2);
    int cb = (lane & 3) * 2;
#pragma unroll
    for (int ntl = 0; ntl < 8; ntl++) {
        int c = nh * 64 + ntl * 8 + cb;
        float bb0 = __ldg(b1g + l * 128 + c);
        float bb1 = __ldg(b1g + l * 128 + c + 1);
        float v00 = fmaxf(acc[ntl * 4 + 0] + bb0, 0.f);
        float v01 = fmaxf(acc[ntl * 4 + 1] + bb1, 0.f);
        float v10 = fmaxf(acc[ntl * 4 + 2] + bb0, 0.f);
        float v11 = fmaxf(acc[ntl * 4 + 3] + bb1, 0.f);
        uint32_t h0, l0, h1, l1;
        split2(v00, v01, h0, l0);
        split2(v10, v11, h1, l1);
        *(uint32_t*)&sAhi[r0 * PA + c] = h0;
        *(uint32_t*)&sAlo[r0 * PA + c] = l0;
        *(uint32_t*)&sAhi[(r0 + 8) * PA + c] = h1;
        *(uint32_t*)&sAlo[(r0 + 8) * PA + c] = l1;
        acc[ntl * 4 + 0] = 0.f; acc[ntl * 4 + 1] = 0.f;
        acc[ntl * 4 + 2] = 0.f; acc[ntl * 4 + 3] = 0.f;
    }
    __syncthreads();   // gemm2 reads cols written by the other column-half warp

    gemm_tile16(sAhi, sAlo, gW2, acc, lane, mrow, ntbase);
    __syncthreads();   // all warps done reading sA before sZ overwrite

    // epilogue 2: z = mask * (acc + b2) + x_in
    bool ok0 = (base + r0) < NN;
    bool ok1 = (base + r0 + 8) < NN;
    float m0 = ok0 ? __ldg(masks + (size_t)l * NN + base + r0) : 0.f;
    float m1 = ok1 ? __ldg(masks + (size_t)l * NN + base + r0 + 8) : 0.f;
#pragma unroll
    for (int ntl = 0; ntl < 8; ntl++) {
        int c = nh * 64 + ntl * 8 + cb;
        float bb0 = __ldg(b2g + l * 128 + c);
        float bb1 = __ldg(b2g + l * 128 + c + 1);
        float2 x0 = ok0 ? *(const float2*)(xin + (size_t)(base + r0) * 128 + c)
                        : make_float2(0.f, 0.f);
        float2 x1 = ok1 ? *(const float2*)(xin + (size_t)(base + r0 + 8) * 128 + c)
                        : make_float2(0.f, 0.f);
        float z00 = m0 * (acc[ntl * 4 + 0] + bb0) + x0.x;
        float z01 = m0 * (acc[ntl * 4 + 1] + bb1) + x0.y;
        float z10 = m1 * (acc[ntl * 4 + 2] + bb0) + x1.x;
        float z11 = m1 * (acc[ntl * 4 + 3] + bb1) + x1.y;
        *(float2*)&sZ[r0 * 128 + c] = make_float2(z00, z01);
        *(float2*)&sZ[(r0 + 8) * 128 + c] = make_float2(z10, z11);
    }
    __syncthreads();

    // BN column partials over valid rows (4 quarters of 32 rows)
    {
        int c = tid & 127, q4 = tid >> 7;
        int rbeg = q4 * 32;
        int rend = min(rbeg + 32, rows);
        float s = 0.f, q = 0.f;
        for (int r = rbeg; r < rend; ++r) {
            float v = sZ[r * 128 + c];
            s += v; q += v * v;
        }
        atomicAdd(&g_bsum[l][c], s);
        atomicAdd(&g_bsq[l][c], q);
    }
    // write z tile
    for (int i = tid; i < rows * 32; i += 512) {
        int r = i >> 5, c4 = i & 31;
        ((float4*)(g_z + (size_t)(base + r) * 128))[c4] = ((const float4*)(sZ + r * 128))[c4];
    }
}

// ---------------- BN finalize + apply + relu ----------------
__global__ void k_bn_apply(int l, float* __restrict__ outp,
                           const float* __restrict__ gamma,
                           const float* __restrict__ beta, int last) {
    int idx = blockIdx.x * blockDim.x + threadIdx.x;
    if (idx >= NN * 32) return;
    float* o = last ? outp : g_h;
    int c4 = idx & 31;
    int c = c4 * 4;
    float4 z = ((const float4*)g_z)[idx];
    float invN = 1.f / (float)NN;
    float4 r;
    {
        float mu = g_bsum[l][c + 0] * invN;
        float var = g_bsq[l][c + 0] * invN - mu * mu;
        r.x = fmaxf(__ldg(gamma + l * 128 + c + 0) * (z.x - mu) * rsqrtf(var + BN_EPS) + __ldg(beta + l * 128 + c + 0), 0.f);
    }
    {
        float mu = g_bsum[l][c + 1] * invN;
        float var = g_bsq[l][c + 1] * invN - mu * mu;
        r.y = fmaxf(__ldg(gamma + l * 128 + c + 1) * (z.y - mu) * rsqrtf(var + BN_EPS) + __ldg(beta + l * 128 + c + 1), 0.f);
    }
    {
        float mu = g_bsum[l][c + 2] * invN;
        float var = g_bsq[l][c + 2] * invN - mu * mu;
        r.z = fmaxf(__ldg(gamma + l * 128 + c + 2) * (z.z - mu) * rsqrtf(var + BN_EPS) + __ldg(beta + l * 128 + c + 2), 0.f);
    }
    {
        float mu = g_bsum[l][c + 3] * invN;
        float var = g_bsq[l][c + 3] * invN - mu * mu;
        r.w = fmaxf(__ldg(gamma + l * 128 + c + 3) * (z.w - mu) * rsqrtf(var + BN_EPS) + __ldg(beta + l * 128 + c + 3), 0.f);
    }
    ((float4*)o)[idx] = r;
}

// ---------------- launch ----------------
extern "C" void kernel_launch(void* const* d_in, const int* in_sizes, int n_in,
                              void* d_out, int out_size) {
    const float* x     = (const float*)d_in[0];
    const float* ea    = (const float*)d_in[1];
    const float* masks = (const float*)d_in[2];
    const int*   ei    = (const int*)d_in[3];
    const float* eps   = (const float*)d_in[4];
    const float* W1    = (const float*)d_in[5];
    const float* b1    = (const float*)d_in[6];
    const float* W2    = (const float*)d_in[7];
    const float* b2    = (const float*)d_in[8];
    const float* gamma = (const float*)d_in[9];
    const float* beta  = (const float*)d_in[10];
    float* out = (float*)d_out;

    cudaFuncSetAttribute(k_mlp, cudaFuncAttributeMaxDynamicSharedMemorySize, SMEM_BYTES);

    k_zero<<<(NN + 255) / 256, 256>>>(W1, W2);
    k_scat<<<(NE + 255) / 256, 256>>>(ei, ei + NE);

    for (int l = 0; l < 3; l++) {
        int first = (l == 0) ? 1 : 0;
        int last = (l == 2) ? 1 : 0;
        k_agg<<<(NN + 7) / 8, 256>>>(x, ea, eps, l, first);
        k_mlp<<<NT, 512, SMEM_BYTES>>>(l, x, masks, b1, b2, first);
        k_bn_apply<<<(NN * 32 + 255) / 256, 256>>>(l, out, gamma, beta, last);
    }
}